// round 2
// baseline (speedup 1.0000x reference)
#include <cuda_runtime.h>
#include <stdint.h>

#define QBINS 313
#define HWC   9216          // 96*96
#define MTOT  294912
#define TPB   256
#define PPT   4
#define NBLK  (MTOT / (TPB * PPT))   // 288

__device__ float    g_partial[NBLK];
__device__ unsigned g_count = 0;

typedef unsigned long long u64;
typedef unsigned int       u32;

// ---- packed f32x2 helpers (Blackwell FFMA2 path) ----
__device__ __forceinline__ u64 pk(float a, float b) {
    u64 r; asm("mov.b64 %0,{%1,%2};" : "=l"(r) : "f"(a), "f"(b)); return r;
}
__device__ __forceinline__ void upkf(u64 v, float& a, float& b) {
    asm("mov.b64 {%0,%1},%2;" : "=f"(a), "=f"(b) : "l"(v));
}
__device__ __forceinline__ void upki(u64 v, u32& a, u32& b) {
    asm("mov.b64 {%0,%1},%2;" : "=r"(a), "=r"(b) : "l"(v));
}
__device__ __forceinline__ u64 pki(u32 a, u32 b) {
    u64 r; asm("mov.b64 %0,{%1,%2};" : "=l"(r) : "r"(a), "r"(b)); return r;
}
__device__ __forceinline__ u64 f2mul(u64 a, u64 b) {
    u64 r; asm("mul.rn.f32x2 %0,%1,%2;" : "=l"(r) : "l"(a), "l"(b)); return r;
}
__device__ __forceinline__ u64 f2add(u64 a, u64 b) {
    u64 r; asm("add.rn.f32x2 %0,%1,%2;" : "=l"(r) : "l"(a), "l"(b)); return r;
}
__device__ __forceinline__ u64 f2fma(u64 a, u64 b, u64 c) {
    u64 r; asm("fma.rn.f32x2 %0,%1,%2,%3;" : "=l"(r) : "l"(a), "l"(b), "l"(c)); return r;
}

__global__ void __launch_bounds__(TPB)
loss_main(const float* __restrict__ pred,      // (B, Q, H, W)
          const float* __restrict__ tgt,       // (B, 2, H, W)
          const float* __restrict__ centers,   // (Q, 2)
          const float* __restrict__ cw,        // (Q,)
          float* __restrict__ out)
{
    __shared__ float4 s_c[QBINS];     // (cx, cy, |c|^2/2, class_weight)
    __shared__ float  s_red[TPB / 32];
    __shared__ float  s_fin[TPB];
    __shared__ bool   s_last;

    const int tid = threadIdx.x;
    for (int i = tid; i < QBINS; i += TPB) {
        float2 c = reinterpret_cast<const float2*>(centers)[i];
        float h = fmaf(0.5f * c.x, c.x, 0.5f * c.y * c.y);
        s_c[i] = make_float4(c.x, c.y, h, cw[i]);
    }
    __syncthreads();

    const int g   = blockIdx.x * TPB + tid;
    const int m0  = g * PPT;
    const int b   = m0 / HWC;
    const int rem = m0 - b * HWC;

    const float4 av = *reinterpret_cast<const float4*>(tgt + (size_t)(2 * b)     * HWC + rem);
    const float4 bv = *reinterpret_cast<const float4*>(tgt + (size_t)(2 * b + 1) * HWC + rem);
    float aa[4] = {av.x * 128.f, av.y * 128.f, av.z * 128.f, av.w * 128.f};
    float bb[4] = {bv.x * 128.f, bv.y * 128.f, bv.z * 128.f, bv.w * 128.f};
    float up[4];                 // |p|^2/2 + 0.5 bias (keeps key positive, exact ranking)
    #pragma unroll
    for (int p = 0; p < 4; ++p)
        up[p] = fmaf(0.5f * aa[p], aa[p], fmaf(0.5f * bb[p], bb[p], 0.5f));

    // top-5 keys: (float_bits(d2/2 + 0.5) & ~0x1FF) | q  (uint-monotone in d2)
    u32 k0[4], k1[4], k2[4], k3[4], k4[4];
    #pragma unroll
    for (int p = 0; p < 4; ++p) { k0[p]=k1[p]=k2[p]=k3[p]=k4[p]=0xFFFFFFFFu; }

    const float*  gbase = pred + (size_t)b * QBINS * HWC + rem;
    const float4* p4    = reinterpret_cast<const float4*>(gbase);

    const u64 L2E = pk(1.4426950408889634f, 1.4426950408889634f);
    const u64 CB  = pk(12582912.0f, 12582912.0f);
    const u64 CNB = pk(-12582912.0f, -12582912.0f);
    const u64 M1  = pk(-1.0f, -1.0f);
    const u64 C5  = pk(1.3333558146e-3f, 1.3333558146e-3f);
    const u64 C4  = pk(9.6181291076e-3f, 9.6181291076e-3f);
    const u64 C3  = pk(5.5504108665e-2f, 5.5504108665e-2f);
    const u64 C2  = pk(2.4022650696e-1f, 2.4022650696e-1f);
    const u64 C1  = pk(6.9314718056e-1f, 6.9314718056e-1f);
    const u64 C0  = pk(1.0f, 1.0f);

    u64 S01 = 0ull, S23 = 0ull;   // packed fp32 accumulators (0.0f bits == 0)

    // ---- single fused pass over q: streaming softmax sum + top-5 selection ----
    #pragma unroll 4
    for (int q = 0; q < QBINS; ++q) {
        float4 v = p4[(size_t)q * (HWC / 4)];
        float4 c = s_c[q];

        // selection (alu pipe: 10 ops/pixel; fma pipe: 3 ops/pixel)
        #pragma unroll
        for (int p = 0; p < 4; ++p) {
            float e = fmaf(-aa[p], c.x, fmaf(-bb[p], c.y, c.z)) + up[p];  // d2/2 + 0.5
            u32 key = (__float_as_uint(e) & 0xFFFFFE00u) | (u32)q;
            u32 lo, hi;
            k4[p] = min(k4[p], key);
            lo = min(k3[p], k4[p]); hi = max(k3[p], k4[p]); k3[p] = lo; k4[p] = hi;
            lo = min(k2[p], k3[p]); hi = max(k2[p], k3[p]); k2[p] = lo; k3[p] = hi;
            lo = min(k1[p], k2[p]); hi = max(k1[p], k2[p]); k1[p] = lo; k2[p] = hi;
            lo = min(k0[p], k1[p]); hi = max(k0[p], k1[p]); k0[p] = lo; k1[p] = hi;
        }

        // packed exp2-based exp for 4 lanes (2 x f32x2 chains, fma pipe)
        {
            u64 T = f2mul(pk(v.x, v.y), L2E);
            u64 Z = f2add(T, CB);
            u64 W = f2add(Z, CNB);              // rint(t)
            u64 R = f2fma(W, M1, T);            // t - rint(t), in [-0.5, 0.5]
            u64 P = f2fma(C5, R, C4);
            P = f2fma(P, R, C3);
            P = f2fma(P, R, C2);
            P = f2fma(P, R, C1);
            P = f2fma(P, R, C0);
            u32 zi0, zi1, pi0, pi1;
            upki(Z, zi0, zi1); upki(P, pi0, pi1);
            S01 = f2add(S01, pki(pi0 + (zi0 << 23), pi1 + (zi1 << 23)));
        }
        {
            u64 T = f2mul(pk(v.z, v.w), L2E);
            u64 Z = f2add(T, CB);
            u64 W = f2add(Z, CNB);
            u64 R = f2fma(W, M1, T);
            u64 P = f2fma(C5, R, C4);
            P = f2fma(P, R, C3);
            P = f2fma(P, R, C2);
            P = f2fma(P, R, C1);
            P = f2fma(P, R, C0);
            u32 zi0, zi1, pi0, pi1;
            upki(Z, zi0, zi1); upki(P, pi0, pi1);
            S23 = f2add(S23, pki(pi0 + (zi0 << 23), pi1 + (zi1 << 23)));
        }
    }

    // ---- per-pixel epilogue: weights (exact d2), gather 5 logits, combine ----
    float Sp[4];
    upkf(S01, Sp[0], Sp[1]);
    upkf(S23, Sp[2], Sp[3]);

    float part = 0.f;
    #pragma unroll
    for (int p = 0; p < 4; ++p) {
        u32 kk[5] = {k0[p], k1[p], k2[p], k3[p], k4[p]};
        float wk[5];
        int   idx[5];
        float wsum = 0.f;
        #pragma unroll
        for (int j = 0; j < 5; ++j) {
            idx[j] = (int)(kk[j] & 511u);
            float4 c = s_c[idx[j]];
            float da = aa[p] - c.x;
            float db = bb[p] - c.y;
            float d2 = fmaf(da, da, db * db);
            float w  = __expf(-0.02f * d2);     // exp(-d2/(2*sigma^2)), sigma=5
            wk[j] = w;
            wsum += w;
        }
        float inv = 1.0f / (wsum + 1e-8f);
        float dot = 0.f;
        #pragma unroll
        for (int j = 0; j < 5; ++j) {
            float x = __ldg(gbase + (size_t)idx[j] * HWC + p);
            dot = fmaf(wk[j], x, dot);
        }
        float lse = __logf(Sp[p]);
        float pw  = s_c[k0[p] & 511u].w;
        part += (lse * (wsum * inv) - dot * inv) * pw;
    }

    // ---- deterministic block reduction ----
    #pragma unroll
    for (int o = 16; o > 0; o >>= 1)
        part += __shfl_down_sync(0xFFFFFFFFu, part, o);
    if ((tid & 31) == 0) s_red[tid >> 5] = part;
    __syncthreads();

    if (tid == 0) {
        float bsum = 0.f;
        #pragma unroll
        for (int w = 0; w < TPB / 32; ++w) bsum += s_red[w];
        g_partial[blockIdx.x] = bsum;
        __threadfence();
        unsigned t = atomicAdd(&g_count, 1u);
        s_last = (t == NBLK - 1);
    }
    __syncthreads();

    // ---- last block finalizes (deterministic fixed-order tree) ----
    if (s_last) {
        float v = 0.f;
        if (tid        < NBLK) v += g_partial[tid];
        if (tid + TPB  < NBLK) v += g_partial[tid + TPB];
        s_fin[tid] = v;
        __syncthreads();
        #pragma unroll
        for (int s = TPB / 2; s > 0; s >>= 1) {
            if (tid < s) s_fin[tid] += s_fin[tid + s];
            __syncthreads();
        }
        if (tid == 0) {
            out[0] = s_fin[0] * (1.0f / (float)MTOT);
            g_count = 0;   // reset for next graph replay
        }
    }
}

extern "C" void kernel_launch(void* const* d_in, const int* in_sizes, int n_in,
                              void* d_out, int out_size) {
    const float* pred    = (const float*)d_in[0];   // (32,313,96,96)
    const float* tgt     = (const float*)d_in[1];   // (32,2,96,96)
    const float* centers = (const float*)d_in[2];   // (313,2)
    const float* cw      = (const float*)d_in[3];   // (313,)
    (void)in_sizes; (void)n_in; (void)out_size;

    loss_main<<<NBLK, TPB>>>(pred, tgt, centers, cw, (float*)d_out);
}

// round 3
// speedup vs baseline: 1.2073x; 1.2073x over previous
#include <cuda_runtime.h>
#include <stdint.h>

#define QBINS 313
#define HWC   9216          // 96*96
#define MTOT  294912
#define TPB   256
#define PPT   2
#define NBLK  (MTOT / (TPB * PPT))   // 576

__device__ float    g_partial[NBLK];
__device__ unsigned g_count = 0;

typedef unsigned long long u64;
typedef unsigned int       u32;

// ---- packed f32x2 helpers (Blackwell FFMA2 path) ----
__device__ __forceinline__ u64 pk(float a, float b) {
    u64 r; asm("mov.b64 %0,{%1,%2};" : "=l"(r) : "f"(a), "f"(b)); return r;
}
__device__ __forceinline__ void upkf(u64 v, float& a, float& b) {
    asm("mov.b64 {%0,%1},%2;" : "=f"(a), "=f"(b) : "l"(v));
}
__device__ __forceinline__ void upki(u64 v, u32& a, u32& b) {
    asm("mov.b64 {%0,%1},%2;" : "=r"(a), "=r"(b) : "l"(v));
}
__device__ __forceinline__ u64 pki(u32 a, u32 b) {
    u64 r; asm("mov.b64 %0,{%1,%2};" : "=l"(r) : "r"(a), "r"(b)); return r;
}
__device__ __forceinline__ u64 f2mul(u64 a, u64 b) {
    u64 r; asm("mul.rn.f32x2 %0,%1,%2;" : "=l"(r) : "l"(a), "l"(b)); return r;
}
__device__ __forceinline__ u64 f2add(u64 a, u64 b) {
    u64 r; asm("add.rn.f32x2 %0,%1,%2;" : "=l"(r) : "l"(a), "l"(b)); return r;
}
__device__ __forceinline__ u64 f2fma(u64 a, u64 b, u64 c) {
    u64 r; asm("fma.rn.f32x2 %0,%1,%2,%3;" : "=l"(r) : "l"(a), "l"(b), "l"(c)); return r;
}

__global__ void __launch_bounds__(TPB)
loss_main(const float* __restrict__ pred,      // (B, Q, H, W)
          const float* __restrict__ tgt,       // (B, 2, H, W)
          const float* __restrict__ centers,   // (Q, 2)
          const float* __restrict__ cw,        // (Q,)
          float* __restrict__ out)
{
    __shared__ float4 s_c[QBINS];     // (cx, cy, |c|^2/2, class_weight)
    __shared__ float  s_red[TPB / 32];
    __shared__ float  s_fin[TPB];
    __shared__ bool   s_last;

    const int tid = threadIdx.x;
    for (int i = tid; i < QBINS; i += TPB) {
        float2 c = reinterpret_cast<const float2*>(centers)[i];
        float h = fmaf(0.5f * c.x, c.x, 0.5f * c.y * c.y);
        s_c[i] = make_float4(c.x, c.y, h, cw[i]);
    }
    __syncthreads();

    const int g   = blockIdx.x * TPB + tid;
    const int m0  = g * PPT;
    const int b   = m0 / HWC;
    const int rem = m0 - b * HWC;

    const float2 av = *reinterpret_cast<const float2*>(tgt + (size_t)(2 * b)     * HWC + rem);
    const float2 bv = *reinterpret_cast<const float2*>(tgt + (size_t)(2 * b + 1) * HWC + rem);
    float aa[PPT] = {av.x * 128.f, av.y * 128.f};
    float bb[PPT] = {bv.x * 128.f, bv.y * 128.f};
    float up[PPT];               // |p|^2/2 + 0.5 (keeps key positive, fine quantization)
    #pragma unroll
    for (int p = 0; p < PPT; ++p)
        up[p] = fmaf(0.5f * aa[p], aa[p], fmaf(0.5f * bb[p], bb[p], 0.5f));

    // top-5 keys: (float_bits(d2/2 + 0.5) & ~0x1FF) | q  (uint-monotone in d2)
    u32 k0[PPT], k1[PPT], k2[PPT], k3[PPT], k4[PPT];
    #pragma unroll
    for (int p = 0; p < PPT; ++p) { k0[p]=k1[p]=k2[p]=k3[p]=k4[p]=0xFFFFFFFFu; }

    const float*  gbase = pred + (size_t)b * QBINS * HWC + rem;
    const float2* p2    = reinterpret_cast<const float2*>(gbase);

    const u64 L2E = pk(1.4426950408889634f, 1.4426950408889634f);
    const u64 CB  = pk(12582912.0f, 12582912.0f);
    const u64 CNB = pk(-12582912.0f, -12582912.0f);
    const u64 M1  = pk(-1.0f, -1.0f);
    const u64 C5  = pk(1.3333558146e-3f, 1.3333558146e-3f);
    const u64 C4  = pk(9.6181291076e-3f, 9.6181291076e-3f);
    const u64 C3  = pk(5.5504108665e-2f, 5.5504108665e-2f);
    const u64 C2  = pk(2.4022650696e-1f, 2.4022650696e-1f);
    const u64 C1  = pk(6.9314718056e-1f, 6.9314718056e-1f);
    const u64 C0  = pk(1.0f, 1.0f);

    u64 S01 = 0ull;   // packed fp32 accumulator for the 2 pixels

    // ---- single fused pass over q: streaming softmax sum + top-5 selection ----
    #pragma unroll 4
    for (int q = 0; q < QBINS; ++q) {
        float2 v = p2[(size_t)q * (HWC / 2)];
        float4 c = s_c[q];

        #pragma unroll
        for (int p = 0; p < PPT; ++p) {
            float e = fmaf(-aa[p], c.x, fmaf(-bb[p], c.y, c.z)) + up[p];  // d2/2 + 0.5
            u32 key = (__float_as_uint(e) & 0xFFFFFE00u) | (u32)q;
            u32 lo, hi;
            k4[p] = min(k4[p], key);
            lo = min(k3[p], k4[p]); hi = max(k3[p], k4[p]); k3[p] = lo; k4[p] = hi;
            lo = min(k2[p], k3[p]); hi = max(k2[p], k3[p]); k2[p] = lo; k3[p] = hi;
            lo = min(k1[p], k2[p]); hi = max(k1[p], k2[p]); k1[p] = lo; k2[p] = hi;
            lo = min(k0[p], k1[p]); hi = max(k0[p], k1[p]); k0[p] = lo; k1[p] = hi;
        }

        // packed exp2-based exp for both pixels (one f32x2 chain, fma pipe)
        u64 T = f2mul(pk(v.x, v.y), L2E);
        u64 Z = f2add(T, CB);
        u64 W = f2add(Z, CNB);              // rint(t)
        u64 R = f2fma(W, M1, T);            // t - rint(t), in [-0.5, 0.5]
        u64 P = f2fma(C5, R, C4);
        P = f2fma(P, R, C3);
        P = f2fma(P, R, C2);
        P = f2fma(P, R, C1);
        P = f2fma(P, R, C0);
        u32 zi0, zi1, pi0, pi1;
        upki(Z, zi0, zi1); upki(P, pi0, pi1);
        S01 = f2add(S01, pki(pi0 + (zi0 << 23), pi1 + (zi1 << 23)));
    }

    // ---- per-pixel epilogue: weights (exact d2), gather 5 logits, combine ----
    float Sp[PPT];
    upkf(S01, Sp[0], Sp[1]);

    float part = 0.f;
    #pragma unroll
    for (int p = 0; p < PPT; ++p) {
        u32 kk[5] = {k0[p], k1[p], k2[p], k3[p], k4[p]};
        float wk[5];
        int   idx[5];
        float wsum = 0.f;
        #pragma unroll
        for (int j = 0; j < 5; ++j) {
            idx[j] = (int)(kk[j] & 511u);
            float4 c = s_c[idx[j]];
            float da = aa[p] - c.x;
            float db = bb[p] - c.y;
            float d2 = fmaf(da, da, db * db);
            float w  = __expf(-0.02f * d2);     // exp(-d2/(2*sigma^2)), sigma=5
            wk[j] = w;
            wsum += w;
        }
        float inv = 1.0f / (wsum + 1e-8f);
        float dot = 0.f;
        #pragma unroll
        for (int j = 0; j < 5; ++j) {
            float x = __ldg(gbase + (size_t)idx[j] * HWC + p);
            dot = fmaf(wk[j], x, dot);
        }
        float lse = __logf(Sp[p]);
        float pw  = s_c[k0[p] & 511u].w;
        part += (lse * (wsum * inv) - dot * inv) * pw;
    }

    // ---- deterministic block reduction ----
    #pragma unroll
    for (int o = 16; o > 0; o >>= 1)
        part += __shfl_down_sync(0xFFFFFFFFu, part, o);
    if ((tid & 31) == 0) s_red[tid >> 5] = part;
    __syncthreads();

    if (tid == 0) {
        float bsum = 0.f;
        #pragma unroll
        for (int w = 0; w < TPB / 32; ++w) bsum += s_red[w];
        g_partial[blockIdx.x] = bsum;
        __threadfence();
        unsigned t = atomicAdd(&g_count, 1u);
        s_last = (t == NBLK - 1);
    }
    __syncthreads();

    // ---- last block finalizes (deterministic fixed-order tree) ----
    if (s_last) {
        float v = 0.f;
        #pragma unroll
        for (int base = 0; base < NBLK; base += TPB)
            if (base + tid < NBLK) v += g_partial[base + tid];
        s_fin[tid] = v;
        __syncthreads();
        #pragma unroll
        for (int s = TPB / 2; s > 0; s >>= 1) {
            if (tid < s) s_fin[tid] += s_fin[tid + s];
            __syncthreads();
        }
        if (tid == 0) {
            out[0] = s_fin[0] * (1.0f / (float)MTOT);
            g_count = 0;   // reset for next graph replay
        }
    }
}

extern "C" void kernel_launch(void* const* d_in, const int* in_sizes, int n_in,
                              void* d_out, int out_size) {
    const float* pred    = (const float*)d_in[0];   // (32,313,96,96)
    const float* tgt     = (const float*)d_in[1];   // (32,2,96,96)
    const float* centers = (const float*)d_in[2];   // (313,2)
    const float* cw      = (const float*)d_in[3];   // (313,)
    (void)in_sizes; (void)n_in; (void)out_size;

    loss_main<<<NBLK, TPB>>>(pred, tgt, centers, cw, (float*)d_out);
}